// round 6
// baseline (speedup 1.0000x reference)
#include <cuda_runtime.h>
#include <cuda_fp16.h>
#include <math.h>
#include <stdint.h>

// Problem dims
#define BB   2
#define LL   2048
#define DM   1024
#define DI   2048
#define NS   16
#define RR   64
#define XD   96            // R + 2N
#define MR   (BB*LL)       // 4096 rows
#define EPSV 1e-5f
#define XKS  8             // split-K factor for x_proj

// ---------------- scratch (no alloc allowed) ----------------
__device__ __align__(128) float g_xz  [(size_t)MR * 2 * DI];
__device__ __align__(128) float g_xd  [(size_t)MR * XD];
__device__ __align__(128) float g_xdp [(size_t)XKS * MR * XD];  // split-K partials
__device__ __align__(128) float g_dt  [(size_t)MR * DI];

__device__ __align__(128) __half g_h  [(size_t)MR * DM];
__device__ __align__(128) __half g_u  [(size_t)MR * DI];
__device__ __align__(128) __half g_xdh[(size_t)MR * XD];
__device__ __align__(128) __half g_yg [(size_t)MR * DI];
// transposed weights [N,K] fp16
__device__ __align__(128) __half g_wi [(size_t)(2*DI) * DM];
__device__ __align__(128) __half g_wx [(size_t)XD * DI];
__device__ __align__(128) __half g_wd [(size_t)DI * RR];
__device__ __align__(128) __half g_wo [(size_t)DM * DI];

// ================= baseline-PTX helpers =================
__device__ __forceinline__ uint32_t smem_to_u32(const void* p) {
    uint32_t a;
    asm("{ .reg .u64 t; cvta.to.shared.u64 t, %1; cvt.u32.u64 %0, t; }" : "=r"(a) : "l"(p));
    return a;
}
#define CP_ASYNC16(dst, src) \
    asm volatile("cp.async.cg.shared.global [%0], [%1], 16;" :: "r"(dst), "l"(src))
#define CP_ASYNC16_P(dst, src, p) \
    asm volatile("{\n\t.reg .pred q;\n\t.reg .b32 sz;\n\t" \
                 "setp.ne.u32 q, %2, 0;\n\tselp.b32 sz, 16, 0, q;\n\t" \
                 "cp.async.cg.shared.global [%0], [%1], 16, sz;\n\t}" \
                 :: "r"(dst), "l"(src), "r"(p))
#define CP_COMMIT() asm volatile("cp.async.commit_group;" ::: "memory")
#define CP_WAIT(N)  asm volatile("cp.async.wait_group %0;" :: "n"(N) : "memory")
#define LDMX4(r0, r1, r2, r3, addr) \
    asm volatile("ldmatrix.sync.aligned.m8n8.x4.shared.b16 {%0,%1,%2,%3}, [%4];" \
                 : "=r"(r0), "=r"(r1), "=r"(r2), "=r"(r3) : "r"(addr))
#define MMA16816(d, a, b) \
    asm volatile("mma.sync.aligned.m16n8k16.row.col.f32.f16.f16.f32 " \
                 "{%0,%1,%2,%3}, {%4,%5,%6,%7}, {%8,%9}, {%0,%1,%2,%3};" \
                 : "+f"((d)[0]), "+f"((d)[1]), "+f"((d)[2]), "+f"((d)[3]) \
                 : "r"((a)[0]), "r"((a)[1]), "r"((a)[2]), "r"((a)[3]), \
                   "r"((b)[0]), "r"((b)[1]))

// ---------------- math helpers ----------------
__device__ __forceinline__ float softplus_f(float v) {
    return v > 20.f ? v : log1pf(__expf(v));
}
__device__ __forceinline__ float silu_f(float v) {
    return v / (1.f + __expf(-v));
}

// ================= RMSNorm -> fp16 =================
__global__ void rmsnorm_k(const float* __restrict__ x,
                          const float* __restrict__ w,
                          __half* __restrict__ oh) {
    int row = blockIdx.x;
    const float4* xr = (const float4*)(x + (size_t)row * DM);
    float4 v = xr[threadIdx.x];
    float ss = v.x*v.x + v.y*v.y + v.z*v.z + v.w*v.w;
    #pragma unroll
    for (int m = 16; m; m >>= 1) ss += __shfl_xor_sync(~0u, ss, m);
    __shared__ float sred[8];
    __shared__ float stot;
    int wid = threadIdx.x >> 5;
    if ((threadIdx.x & 31) == 0) sred[wid] = ss;
    __syncthreads();
    if (threadIdx.x == 0) {
        float s = 0.f;
        #pragma unroll
        for (int i = 0; i < 8; i++) s += sred[i];
        stot = rsqrtf(s * (1.f / DM) + EPSV);
    }
    __syncthreads();
    float sc = stot;
    float4 wv = ((const float4*)w)[threadIdx.x];
    size_t base = (size_t)row * DM + threadIdx.x * 4;
    oh[base + 0] = __float2half(v.x * sc * wv.x);
    oh[base + 1] = __float2half(v.y * sc * wv.y);
    oh[base + 2] = __float2half(v.z * sc * wv.z);
    oh[base + 3] = __float2half(v.w * sc * wv.w);
}

// ================= transpose + fp16 convert =================
// in [R,C] fp32 -> out [C,R] fp16. R,C multiples of 32.
__global__ void transcvt_k(const float* __restrict__ in, int R, int C,
                           __half* __restrict__ oh) {
    __shared__ float t[32][33];
    int ct = blockIdx.x * 32, rt = blockIdx.y * 32;
    int tx = threadIdx.x & 31, ty4 = (threadIdx.x >> 5) * 4;
    #pragma unroll
    for (int j = 0; j < 4; j++) {
        int r = rt + ty4 + j;
        t[ty4 + j][tx] = in[(size_t)r * C + ct + tx];
    }
    __syncthreads();
    #pragma unroll
    for (int j = 0; j < 4; j++) {
        int c = ct + ty4 + j;
        size_t o = (size_t)c * R + rt + tx;
        oh[o] = __float2half(t[tx][ty4 + j]);
    }
}

// ================= HMMA fp16 GEMM, 6-stage cp.async pipeline ==============
// C[M,N] = A[M,K] @ Bt^T, Bt[N,K] fp16, fp32 accum. 128x128 CTA tile, BK=32,
// 8 warps (4x2), warp tile 32x64.
// EPI 0: plain  1: softplus(v+bias[col])  2: v+resid[row,col]
// EPI 3: fp32 + fp16 stores   4: split-K partial (z slices)
#define SMS    80                    // smem row stride bytes (40 halves)
#define T_B    10240
#define T_STG  20480
#define NSTG   6
#define SMEMB  (NSTG * T_STG)

template<int EPI>
__global__ void __launch_bounds__(256, 1)
mma_gemm_k(const __half* __restrict__ A, int lda,
           const __half* __restrict__ Bt,
           float* __restrict__ C, int ldc, int Kdim, int Ndim,
           const float* __restrict__ bias, const float* __restrict__ resid,
           __half* __restrict__ Ch) {
    extern __shared__ char smem[];
    const uint32_t sdata = smem_to_u32(smem);
    const int tid = threadIdx.x;
    const int wid = tid >> 5, lane = tid & 31;
    const int wm = wid & 3, wn = wid >> 2;          // 4 x 2 warp grid
    const int brow = blockIdx.y * 128;
    const int bcol = blockIdx.x * 128;
    const int kslice = Kdim / gridDim.z;            // gridDim.z==1 unless EPI 4
    const int kbase  = blockIdx.z * kslice;
    const int NC = kslice >> 5;                     // 32-wide K chunks

    const int lrow = tid >> 2;
    const int lseg = tid & 3;

    float acc[2][8][4];
    #pragma unroll
    for (int a = 0; a < 2; a++)
        #pragma unroll
        for (int b = 0; b < 8; b++)
            #pragma unroll
            for (int c = 0; c < 4; c++) acc[a][b][c] = 0.f;

    auto issue = [&](int s) {
        uint32_t stb = sdata + (s % NSTG) * T_STG;
        int koff = kbase + s * 32;
        #pragma unroll
        for (int it = 0; it < 2; it++) {
            int row = it * 64 + lrow;
            uint32_t so = stb + row * SMS + lseg * 16;
            size_t gao = (size_t)(brow + row) * lda + koff + lseg * 8;
            CP_ASYNC16(so, A + gao);
            int bn = bcol + row;
            uint32_t p = (bn < Ndim) ? 1u : 0u;
            size_t gbo = (size_t)bn * Kdim + koff + lseg * 8;
            CP_ASYNC16_P(so + T_B, Bt + gbo, p);
        }
        CP_COMMIT();
    };

    // prefetch NSTG-1 stages
    #pragma unroll
    for (int s = 0; s < NSTG - 1; s++) {
        if (s < NC) issue(s); else CP_COMMIT();
    }

    for (int i = 0; i < NC; i++) {
        CP_WAIT(NSTG - 2);
        __syncthreads();
        if (i + NSTG - 1 < NC) issue(i + NSTG - 1); else CP_COMMIT();

        uint32_t stb = sdata + (i % NSTG) * T_STG;
        const int fr = lane & 15;
        const int fc = (lane >> 4) * 8;
        #pragma unroll
        for (int ks = 0; ks < 32; ks += 16) {
            uint32_t ah[2][4], bh[8][2];
            #pragma unroll
            for (int mt = 0; mt < 2; mt++) {
                uint32_t ad = stb + (wm * 32 + mt * 16 + fr) * SMS + (ks + fc) * 2;
                LDMX4(ah[mt][0], ah[mt][1], ah[mt][2], ah[mt][3], ad);
            }
            #pragma unroll
            for (int bt = 0; bt < 4; bt++) {
                uint32_t bd = stb + T_B + (wn * 64 + bt * 16 + fr) * SMS + (ks + fc) * 2;
                uint32_t r0, r1, r2, r3;
                LDMX4(r0, r1, r2, r3, bd);
                bh[bt*2][0] = r0;   bh[bt*2][1] = r2;
                bh[bt*2+1][0] = r1; bh[bt*2+1][1] = r3;
            }
            #pragma unroll
            for (int mt = 0; mt < 2; mt++)
                #pragma unroll
                for (int nt = 0; nt < 8; nt++)
                    MMA16816(acc[mt][nt], ah[mt], bh[nt]);
        }
    }

    // ---- epilogue ----
    float* Cout = C;
    if (EPI == 4) Cout = C + (size_t)blockIdx.z * MR * XD;
    const int lr = lane >> 2;
    const int lc = (lane & 3) * 2;
    #pragma unroll
    for (int mt = 0; mt < 2; mt++) {
        int r0 = brow + wm * 32 + mt * 16 + lr;
        #pragma unroll
        for (int nt = 0; nt < 8; nt++) {
            int c = bcol + wn * 64 + nt * 8 + lc;
            if (c >= Ndim) continue;
            #pragma unroll
            for (int hh = 0; hh < 2; hh++) {
                int r = r0 + hh * 8;
                float v0 = acc[mt][nt][hh*2], v1 = acc[mt][nt][hh*2+1];
                if (EPI == 1) {
                    v0 = softplus_f(v0 + bias[c]);
                    v1 = softplus_f(v1 + bias[c+1]);
                } else if (EPI == 2) {
                    const float* rr = resid + (size_t)r * ldc + c;
                    v0 += rr[0]; v1 += rr[1];
                }
                float* cp = Cout + (size_t)r * ldc + c;
                *(float2*)cp = make_float2(v0, v1);
                if (EPI == 3) {
                    size_t hb = (size_t)r * ldc + c;
                    Ch[hb]   = __float2half(v0);
                    Ch[hb+1] = __float2half(v1);
                }
            }
        }
    }
}

// ================= split-K reduce for x_proj -> xd fp32 + fp16 ============
__global__ void xd_reduce_k(const float* __restrict__ part,
                            float* __restrict__ xd,
                            __half* __restrict__ xh) {
    size_t i = (size_t)blockIdx.x * 256 + threadIdx.x;
    float s = 0.f;
    #pragma unroll
    for (int z = 0; z < XKS; z++) s += part[(size_t)z * MR * XD + i];
    xd[i] = s;
    xh[i] = __float2half(s);
}

// ================= causal depthwise conv (K=4) + SiLU, L-tiled -> fp16 ====
#define CLT 16
__global__ void conv_silu_k(const float* __restrict__ xz,
                            const float* __restrict__ cw,
                            const float* __restrict__ cb,
                            __half* __restrict__ uh) {
    int d = blockIdx.x * 256 + threadIdx.x;
    int l0 = blockIdx.y * CLT;
    int b = blockIdx.z;
    float4 w = ((const float4*)cw)[d];
    float bias = cb[d];
    const size_t stride = (size_t)2 * DI;
    size_t base = ((size_t)(b * LL) + l0) * stride + d;
    float i3 = (l0 >= 3) ? xz[base - 3 * stride] : 0.f;
    float i2 = (l0 >= 2) ? xz[base - 2 * stride] : 0.f;
    float i1 = (l0 >= 1) ? xz[base - 1 * stride] : 0.f;
    size_t ob = ((size_t)(b * LL) + l0) * DI + d;
    #pragma unroll
    for (int j = 0; j < CLT; j++) {
        float cur = xz[base + (size_t)j * stride];
        float acc = bias;
        acc = fmaf(i3, w.x, acc);
        acc = fmaf(i2, w.y, acc);
        acc = fmaf(i1, w.z, acc);
        acc = fmaf(cur, w.w, acc);
        uh[ob + (size_t)j * DI] = __float2half(silu_f(acc));
        i3 = i2; i2 = i1; i1 = cur;
    }
}

// ================= selective scan + fused gate -> yg fp16 =================
__global__ void __launch_bounds__(256) scan_k(
    const float* __restrict__ xdbl, const float* __restrict__ dt,
    const __half* __restrict__ uh,  const float* __restrict__ xz,
    const float* __restrict__ Alog, const float* __restrict__ Dp,
    __half* __restrict__ yg) {
    __shared__ float sBC[64][32];
    int tid = threadIdx.x;
    int g = tid >> 4, n = tid & 15;
    int b = blockIdx.x >> 7;
    int d = ((blockIdx.x & 127) << 4) + g;
    float An = -expf(Alog[d * NS + n]);
    float Dd = Dp[d];
    float h = 0.f;
    size_t rowbase = (size_t)b * LL;
    for (int c = 0; c < LL / 64; c++) {
        __syncthreads();
        for (int i = tid; i < 64 * 32; i += 256) {
            int tt = i >> 5, col = i & 31;
            sBC[tt][col] = xdbl[(rowbase + c * 64 + tt) * XD + 64 + col];
        }
        __syncthreads();
        for (int tt = 0; tt < 64; tt++) {
            size_t row = rowbase + c * 64 + tt;
            size_t idx = row * DI + d;
            float dtv = __ldg(dt + idx);
            float uv  = __half2float(uh[idx]);
            float Bv = sBC[tt][n];
            float Cv = sBC[tt][16 + n];
            float dA = __expf(dtv * An);
            h = fmaf(dA, h, dtv * Bv * uv);
            float p = h * Cv;
            p += __shfl_xor_sync(0xffffffffu, p, 8, 16);
            p += __shfl_xor_sync(0xffffffffu, p, 4, 16);
            p += __shfl_xor_sync(0xffffffffu, p, 2, 16);
            p += __shfl_xor_sync(0xffffffffu, p, 1, 16);
            if (n == 0) {
                float zv = xz[row * (2 * DI) + DI + d];
                yg[idx] = __float2half((p + uv * Dd) * silu_f(zv));
            }
        }
    }
}

// ================= launcher =================
extern "C" void kernel_launch(void* const* d_in, const int* in_sizes, int n_in,
                              void* d_out, int out_size) {
    const float* x         = (const float*)d_in[0];
    const float* norm_w    = (const float*)d_in[2];
    const float* in_proj_w = (const float*)d_in[3];
    const float* conv_w    = (const float*)d_in[4];
    const float* conv_b    = (const float*)d_in[5];
    const float* x_proj_w  = (const float*)d_in[6];
    const float* dt_proj_w = (const float*)d_in[7];
    const float* dt_proj_b = (const float*)d_in[8];
    const float* A_log     = (const float*)d_in[9];
    const float* Dp        = (const float*)d_in[10];
    const float* out_proj_w= (const float*)d_in[11];
    float* out = (float*)d_out;

    float *xz, *xd, *xdp, *dt;
    cudaGetSymbolAddress((void**)&xz,  g_xz);
    cudaGetSymbolAddress((void**)&xd,  g_xd);
    cudaGetSymbolAddress((void**)&xdp, g_xdp);
    cudaGetSymbolAddress((void**)&dt,  g_dt);
    __half *hh, *uhp, *xdh, *ygp, *wi, *wx, *wd, *wo;
    cudaGetSymbolAddress((void**)&hh,  g_h);
    cudaGetSymbolAddress((void**)&uhp, g_u);
    cudaGetSymbolAddress((void**)&xdh, g_xdh);
    cudaGetSymbolAddress((void**)&ygp, g_yg);
    cudaGetSymbolAddress((void**)&wi,  g_wi);
    cudaGetSymbolAddress((void**)&wx,  g_wx);
    cudaGetSymbolAddress((void**)&wd,  g_wd);
    cudaGetSymbolAddress((void**)&wo,  g_wo);

    cudaFuncSetAttribute(mma_gemm_k<0>, cudaFuncAttributeMaxDynamicSharedMemorySize, SMEMB);
    cudaFuncSetAttribute(mma_gemm_k<1>, cudaFuncAttributeMaxDynamicSharedMemorySize, SMEMB);
    cudaFuncSetAttribute(mma_gemm_k<2>, cudaFuncAttributeMaxDynamicSharedMemorySize, SMEMB);
    cudaFuncSetAttribute(mma_gemm_k<4>, cudaFuncAttributeMaxDynamicSharedMemorySize, SMEMB);

    // 0. weight transpose + fp16 convert
    transcvt_k<<<dim3((2*DI)/32, DM/32), 256>>>(in_proj_w, DM, 2*DI, wi);
    transcvt_k<<<dim3(XD/32, DI/32), 256>>>(x_proj_w, DI, XD, wx);
    transcvt_k<<<dim3(DI/32, RR/32), 256>>>(dt_proj_w, RR, DI, wd);
    transcvt_k<<<dim3(DM/32, DI/32), 256>>>(out_proj_w, DI, DM, wo);
    // 1. h = rmsnorm(x) -> fp16
    rmsnorm_k<<<MR, 256>>>(x, norm_w, hh);
    // 2. xz = h @ in_proj_w  (4096x1024 @ 1024x4096)
    mma_gemm_k<0><<<dim3((2*DI)/128, MR/128), 256, SMEMB>>>(
        hh, DM, wi, xz, 2*DI, DM, 2*DI, nullptr, nullptr, nullptr);
    // 3. u = silu(causal_conv(xz[..., :DI])) -> fp16
    conv_silu_k<<<dim3(DI/256, LL/CLT, BB), 256>>>(xz, conv_w, conv_b, uhp);
    // 4. xdbl = u @ x_proj_w  (4096x2048 @ 2048x96), split-K x8 + reduce
    mma_gemm_k<4><<<dim3(1, MR/128, XKS), 256, SMEMB>>>(
        uhp, DI, wx, xdp, XD, DI, XD, nullptr, nullptr, nullptr);
    xd_reduce_k<<<(MR * XD) / 256, 256>>>(xdp, xd, xdh);
    // 5. dt = softplus(xdbl[:, :64] @ dt_proj_w + b)  (4096x64 @ 64x2048)
    mma_gemm_k<1><<<dim3(DI/128, MR/128), 256, SMEMB>>>(
        xdh, XD, wd, dt, DI, RR, DI, dt_proj_b, nullptr, nullptr);
    // 6. selective scan + fused gate -> yg fp16
    scan_k<<<BB * DI / 16, 256>>>(xd, dt, uhp, xz, A_log, Dp, ygp);
    // 7. out = x + yg @ out_proj_w  (4096x2048 @ 2048x1024)
    mma_gemm_k<2><<<dim3(DM/128, MR/128), 256, SMEMB>>>(
        ygp, DI, wo, out, DM, DI, DM, nullptr, x, nullptr);
}

// round 7
// speedup vs baseline: 1.3871x; 1.3871x over previous
#include <cuda_runtime.h>
#include <cuda_bf16.h>
#include <math.h>
#include <stdint.h>

// Problem dims
#define BB   2
#define LL   2048
#define DM   1024
#define DI   2048
#define NS   16
#define RR   64
#define XD   96            // R + 2N
#define MR   (BB*LL)       // 4096 rows
#define EPSV 1e-5f
#define XKS  8             // split-K factor for x_proj

// ---------------- scratch (no alloc allowed) ----------------
__device__ __align__(128) float g_xz  [(size_t)MR * 2 * DI];
__device__ __align__(128) float g_xd  [(size_t)MR * XD];
__device__ __align__(128) float g_xdp [(size_t)XKS * MR * XD];  // split-K partials
__device__ __align__(128) float g_dt  [(size_t)MR * DI];

__device__ __align__(128) __nv_bfloat16 g_h_hi [(size_t)MR * DM];
__device__ __align__(128) __nv_bfloat16 g_h_lo [(size_t)MR * DM];
__device__ __align__(128) __nv_bfloat16 g_u_hi [(size_t)MR * DI];
__device__ __align__(128) __nv_bfloat16 g_u_lo [(size_t)MR * DI];
__device__ __align__(128) __nv_bfloat16 g_xd_hi[(size_t)MR * XD];
__device__ __align__(128) __nv_bfloat16 g_xd_lo[(size_t)MR * XD];
__device__ __align__(128) __nv_bfloat16 g_yg_hi[(size_t)MR * DI];
__device__ __align__(128) __nv_bfloat16 g_yg_lo[(size_t)MR * DI];
// transposed weights [N,K] bf16 hi/lo
__device__ __align__(128) __nv_bfloat16 g_wi_hi[(size_t)(2*DI) * DM];
__device__ __align__(128) __nv_bfloat16 g_wi_lo[(size_t)(2*DI) * DM];
__device__ __align__(128) __nv_bfloat16 g_wx_hi[(size_t)XD * DI];
__device__ __align__(128) __nv_bfloat16 g_wx_lo[(size_t)XD * DI];
__device__ __align__(128) __nv_bfloat16 g_wd_hi[(size_t)DI * RR];
__device__ __align__(128) __nv_bfloat16 g_wd_lo[(size_t)DI * RR];
__device__ __align__(128) __nv_bfloat16 g_wo_hi[(size_t)DM * DI];
__device__ __align__(128) __nv_bfloat16 g_wo_lo[(size_t)DM * DI];

// ================= baseline-PTX helpers (no sm_103a-only ops) =============
__device__ __forceinline__ uint32_t smem_to_u32(const void* p) {
    uint32_t a;
    asm("{ .reg .u64 t; cvta.to.shared.u64 t, %1; cvt.u32.u64 %0, t; }" : "=r"(a) : "l"(p));
    return a;
}
#define CP_ASYNC16(dst, src) \
    asm volatile("cp.async.cg.shared.global [%0], [%1], 16;" :: "r"(dst), "l"(src))
#define CP_ASYNC16_P(dst, src, p) \
    asm volatile("{\n\t.reg .pred q;\n\t.reg .b32 sz;\n\t" \
                 "setp.ne.u32 q, %2, 0;\n\tselp.b32 sz, 16, 0, q;\n\t" \
                 "cp.async.cg.shared.global [%0], [%1], 16, sz;\n\t}" \
                 :: "r"(dst), "l"(src), "r"(p))
#define CP_COMMIT() asm volatile("cp.async.commit_group;" ::: "memory")
#define CP_WAIT(N)  asm volatile("cp.async.wait_group %0;" :: "n"(N) : "memory")
#define LDMX4(r0, r1, r2, r3, addr) \
    asm volatile("ldmatrix.sync.aligned.m8n8.x4.shared.b16 {%0,%1,%2,%3}, [%4];" \
                 : "=r"(r0), "=r"(r1), "=r"(r2), "=r"(r3) : "r"(addr))
#define MMA16816(d, a, b) \
    asm volatile("mma.sync.aligned.m16n8k16.row.col.f32.bf16.bf16.f32 " \
                 "{%0,%1,%2,%3}, {%4,%5,%6,%7}, {%8,%9}, {%0,%1,%2,%3};" \
                 : "+f"((d)[0]), "+f"((d)[1]), "+f"((d)[2]), "+f"((d)[3]) \
                 : "r"((a)[0]), "r"((a)[1]), "r"((a)[2]), "r"((a)[3]), \
                   "r"((b)[0]), "r"((b)[1]))

// ---------------- math helpers ----------------
__device__ __forceinline__ float softplus_f(float v) {
    return v > 20.f ? v : log1pf(__expf(v));
}
__device__ __forceinline__ float silu_f(float v) {
    return v / (1.f + __expf(-v));
}
__device__ __forceinline__ void split_bf16(float v, __nv_bfloat16& hi, __nv_bfloat16& lo) {
    hi = __float2bfloat16(v);
    lo = __float2bfloat16(v - __bfloat162float(hi));
}

// ================= RMSNorm -> bf16 hi/lo =================
__global__ void rmsnorm_k(const float* __restrict__ x,
                          const float* __restrict__ w,
                          __nv_bfloat16* __restrict__ ohi,
                          __nv_bfloat16* __restrict__ olo) {
    int row = blockIdx.x;
    const float4* xr = (const float4*)(x + (size_t)row * DM);
    float4 v = xr[threadIdx.x];
    float ss = v.x*v.x + v.y*v.y + v.z*v.z + v.w*v.w;
    #pragma unroll
    for (int m = 16; m; m >>= 1) ss += __shfl_xor_sync(~0u, ss, m);
    __shared__ float sred[8];
    __shared__ float stot;
    int wid = threadIdx.x >> 5;
    if ((threadIdx.x & 31) == 0) sred[wid] = ss;
    __syncthreads();
    if (threadIdx.x == 0) {
        float s = 0.f;
        #pragma unroll
        for (int i = 0; i < 8; i++) s += sred[i];
        stot = rsqrtf(s * (1.f / DM) + EPSV);
    }
    __syncthreads();
    float sc = stot;
    float4 wv = ((const float4*)w)[threadIdx.x];
    float o[4] = {v.x*sc*wv.x, v.y*sc*wv.y, v.z*sc*wv.z, v.w*sc*wv.w};
    size_t base = (size_t)row * DM + threadIdx.x * 4;
    #pragma unroll
    for (int j = 0; j < 4; j++) {
        __nv_bfloat16 hi, lo; split_bf16(o[j], hi, lo);
        ohi[base + j] = hi; olo[base + j] = lo;
    }
}

// ================= transpose + bf16 hi/lo split =================
__global__ void transcvt_k(const float* __restrict__ in, int R, int C,
                           __nv_bfloat16* __restrict__ ohi,
                           __nv_bfloat16* __restrict__ olo) {
    __shared__ float t[32][33];
    int ct = blockIdx.x * 32, rt = blockIdx.y * 32;
    int tx = threadIdx.x & 31, ty4 = (threadIdx.x >> 5) * 4;
    #pragma unroll
    for (int j = 0; j < 4; j++) {
        int r = rt + ty4 + j;
        t[ty4 + j][tx] = in[(size_t)r * C + ct + tx];
    }
    __syncthreads();
    #pragma unroll
    for (int j = 0; j < 4; j++) {
        int c = ct + ty4 + j;
        float v = t[tx][ty4 + j];
        __nv_bfloat16 hi, lo; split_bf16(v, hi, lo);
        size_t o = (size_t)c * R + rt + tx;
        ohi[o] = hi; olo[o] = lo;
    }
}

// ================= HMMA bf16x3 GEMM, 4-stage cp.async pipeline ============
// C[M,N] = A[M,K] @ Bt^T, Bt[N,K]. 128x128 CTA tile, BK=32, 8 warps (4x2),
// warp tile 32x64. (Ahi*Bhi + Ahi*Blo + Alo*Bhi).
// EPI 0: plain  1: softplus(v+bias[col])  2: v+resid[row,col]
// EPI 4: split-K partial (z slices)
#define SMS    80                    // smem row stride bytes (40 halves)
#define T_A_LO 10240
#define T_B_HI 20480
#define T_B_LO 30720
#define T_STG  40960
#define NSTG   4
#define SMEMB  (NSTG * T_STG)

template<int EPI>
__global__ void __launch_bounds__(256, 1)
mma_gemm_k(const __nv_bfloat16* __restrict__ Ahi, const __nv_bfloat16* __restrict__ Alo, int lda,
           const __nv_bfloat16* __restrict__ Bhi, const __nv_bfloat16* __restrict__ Blo,
           float* __restrict__ C, int ldc, int Kdim, int Ndim,
           const float* __restrict__ bias, const float* __restrict__ resid) {
    extern __shared__ char smem[];
    const uint32_t sdata = smem_to_u32(smem);
    const int tid = threadIdx.x;
    const int wid = tid >> 5, lane = tid & 31;
    const int wm = wid & 3, wn = wid >> 2;          // 4 x 2 warp grid
    const int brow = blockIdx.y * 128;
    const int bcol = blockIdx.x * 128;
    const int kslice = Kdim / gridDim.z;            // gridDim.z==1 unless EPI 4
    const int kbase  = blockIdx.z * kslice;
    const int NC = kslice >> 5;                     // 32-wide K chunks

    const int lrow = tid >> 2;
    const int lseg = tid & 3;

    float acc[2][8][4];
    #pragma unroll
    for (int a = 0; a < 2; a++)
        #pragma unroll
        for (int b = 0; b < 8; b++)
            #pragma unroll
            for (int c = 0; c < 4; c++) acc[a][b][c] = 0.f;

    auto issue = [&](int s) {
        uint32_t stb = sdata + (s & (NSTG - 1)) * T_STG;
        int koff = kbase + s * 32;
        #pragma unroll
        for (int it = 0; it < 2; it++) {
            int row = it * 64 + lrow;
            uint32_t so = stb + row * SMS + lseg * 16;
            size_t gao = (size_t)(brow + row) * lda + koff + lseg * 8;
            CP_ASYNC16(so,          Ahi + gao);
            CP_ASYNC16(so + T_A_LO, Alo + gao);
            int bn = bcol + row;
            uint32_t p = (bn < Ndim) ? 1u : 0u;
            size_t gbo = (size_t)bn * Kdim + koff + lseg * 8;
            CP_ASYNC16_P(so + T_B_HI, Bhi + gbo, p);
            CP_ASYNC16_P(so + T_B_LO, Blo + gbo, p);
        }
        CP_COMMIT();
    };

    // prefetch 3 stages
    #pragma unroll
    for (int s = 0; s < NSTG - 1; s++) {
        if (s < NC) issue(s); else CP_COMMIT();
    }

    for (int i = 0; i < NC; i++) {
        CP_WAIT(NSTG - 2);
        __syncthreads();
        if (i + NSTG - 1 < NC) issue(i + NSTG - 1); else CP_COMMIT();

        uint32_t stb = sdata + (i & (NSTG - 1)) * T_STG;
        const int fr = lane & 15;
        const int fc = (lane >> 4) * 8;
        #pragma unroll
        for (int ks = 0; ks < 32; ks += 16) {
            uint32_t ah[2][4], al[2][4], bh[8][2], bl[8][2];
            #pragma unroll
            for (int mt = 0; mt < 2; mt++) {
                uint32_t ad = stb + (wm * 32 + mt * 16 + fr) * SMS + (ks + fc) * 2;
                LDMX4(ah[mt][0], ah[mt][1], ah[mt][2], ah[mt][3], ad);
                LDMX4(al[mt][0], al[mt][1], al[mt][2], al[mt][3], ad + T_A_LO);
            }
            #pragma unroll
            for (int bt = 0; bt < 4; bt++) {
                uint32_t bd = stb + T_B_HI + (wn * 64 + bt * 16 + fr) * SMS + (ks + fc) * 2;
                uint32_t r0, r1, r2, r3;
                LDMX4(r0, r1, r2, r3, bd);
                bh[bt*2][0] = r0; bh[bt*2][1] = r2;
                bh[bt*2+1][0] = r1; bh[bt*2+1][1] = r3;
                LDMX4(r0, r1, r2, r3, bd + (T_B_LO - T_B_HI));
                bl[bt*2][0] = r0; bl[bt*2][1] = r2;
                bl[bt*2+1][0] = r1; bl[bt*2+1][1] = r3;
            }
            #pragma unroll
            for (int mt = 0; mt < 2; mt++)
                #pragma unroll
                for (int nt = 0; nt < 8; nt++) {
                    MMA16816(acc[mt][nt], ah[mt], bh[nt]);
                    MMA16816(acc[mt][nt], ah[mt], bl[nt]);
                    MMA16816(acc[mt][nt], al[mt], bh[nt]);
                }
        }
    }

    // ---- epilogue ----
    float* Cout = C;
    if (EPI == 4) Cout = C + (size_t)blockIdx.z * MR * XD;
    const int lr = lane >> 2;
    const int lc = (lane & 3) * 2;
    #pragma unroll
    for (int mt = 0; mt < 2; mt++) {
        int r0 = brow + wm * 32 + mt * 16 + lr;
        #pragma unroll
        for (int nt = 0; nt < 8; nt++) {
            int c = bcol + wn * 64 + nt * 8 + lc;
            if (c >= Ndim) continue;
            #pragma unroll
            for (int hh = 0; hh < 2; hh++) {
                int r = r0 + hh * 8;
                float v0 = acc[mt][nt][hh*2], v1 = acc[mt][nt][hh*2+1];
                if (EPI == 1) {
                    v0 = softplus_f(v0 + bias[c]);
                    v1 = softplus_f(v1 + bias[c+1]);
                } else if (EPI == 2) {
                    const float* rr = resid + (size_t)r * ldc + c;
                    v0 += rr[0]; v1 += rr[1];
                }
                float* cp = Cout + (size_t)r * ldc + c;
                *(float2*)cp = make_float2(v0, v1);
            }
        }
    }
}

// ================= split-K reduce for x_proj -> xd fp32 + bf16 hi/lo ======
__global__ void xd_reduce_k(const float* __restrict__ part,
                            float* __restrict__ xd,
                            __nv_bfloat16* __restrict__ xhi,
                            __nv_bfloat16* __restrict__ xlo) {
    size_t i = (size_t)blockIdx.x * 256 + threadIdx.x;
    float s = 0.f;
    #pragma unroll
    for (int z = 0; z < XKS; z++) s += part[(size_t)z * MR * XD + i];
    xd[i] = s;
    __nv_bfloat16 hi, lo; split_bf16(s, hi, lo);
    xhi[i] = hi; xlo[i] = lo;
}

// ================= causal depthwise conv (K=4) + SiLU, L-tiled =============
#define CLT 16
__global__ void conv_silu_k(const float* __restrict__ xz,
                            const float* __restrict__ cw,
                            const float* __restrict__ cb,
                            __nv_bfloat16* __restrict__ uhi,
                            __nv_bfloat16* __restrict__ ulo) {
    int d = blockIdx.x * 256 + threadIdx.x;
    int l0 = blockIdx.y * CLT;
    int b = blockIdx.z;
    float4 w = ((const float4*)cw)[d];
    float bias = cb[d];
    const size_t stride = (size_t)2 * DI;
    size_t base = ((size_t)(b * LL) + l0) * stride + d;
    float i3 = (l0 >= 3) ? xz[base - 3 * stride] : 0.f;
    float i2 = (l0 >= 2) ? xz[base - 2 * stride] : 0.f;
    float i1 = (l0 >= 1) ? xz[base - 1 * stride] : 0.f;
    size_t ob = ((size_t)(b * LL) + l0) * DI + d;
    #pragma unroll
    for (int j = 0; j < CLT; j++) {
        float cur = xz[base + (size_t)j * stride];
        float acc = bias;
        acc = fmaf(i3, w.x, acc);
        acc = fmaf(i2, w.y, acc);
        acc = fmaf(i1, w.z, acc);
        acc = fmaf(cur, w.w, acc);
        float u = silu_f(acc);
        __nv_bfloat16 hi, lo; split_bf16(u, hi, lo);
        uhi[ob + (size_t)j * DI] = hi;
        ulo[ob + (size_t)j * DI] = lo;
        i3 = i2; i2 = i1; i1 = cur;
    }
}

// ================= selective scan + fused gate -> yg bf16 hi/lo ===========
__global__ void __launch_bounds__(256) scan_k(
    const float* __restrict__ xdbl, const float* __restrict__ dt,
    const __nv_bfloat16* __restrict__ uhi, const __nv_bfloat16* __restrict__ ulo,
    const float* __restrict__ xz,
    const float* __restrict__ Alog, const float* __restrict__ Dp,
    __nv_bfloat16* __restrict__ yghi, __nv_bfloat16* __restrict__ yglo) {
    __shared__ float sBC[64][32];
    __shared__ float sZ[64][16];
    int tid = threadIdx.x;
    int g = tid >> 4, n = tid & 15;
    int b = blockIdx.x >> 7;
    int d0 = (blockIdx.x & 127) << 4;
    int d = d0 + g;
    float An = -expf(Alog[d * NS + n]);
    float Dd = Dp[d];
    float h = 0.f;
    size_t rowbase = (size_t)b * LL;
    for (int c = 0; c < LL / 64; c++) {
        __syncthreads();
        for (int i = tid; i < 64 * 32; i += 256) {
            int tt = i >> 5, col = i & 31;
            sBC[tt][col] = xdbl[(rowbase + c * 64 + tt) * XD + 64 + col];
        }
        for (int i = tid; i < 64 * 16; i += 256) {
            int tt = i >> 4, col = i & 15;
            sZ[tt][col] = xz[(rowbase + c * 64 + tt) * (2 * DI) + DI + d0 + col];
        }
        __syncthreads();
        for (int tt = 0; tt < 64; tt++) {
            size_t idx = (rowbase + c * 64 + tt) * DI + d;
            float dtv = __ldg(dt + idx);
            float uv  = __bfloat162float(uhi[idx]) + __bfloat162float(ulo[idx]);
            float Bv = sBC[tt][n];
            float Cv = sBC[tt][16 + n];
            float dA = __expf(dtv * An);
            h = fmaf(dA, h, dtv * Bv * uv);
            float p = h * Cv;
            p += __shfl_xor_sync(0xffffffffu, p, 8, 16);
            p += __shfl_xor_sync(0xffffffffu, p, 4, 16);
            p += __shfl_xor_sync(0xffffffffu, p, 2, 16);
            p += __shfl_xor_sync(0xffffffffu, p, 1, 16);
            if (n == 0) {
                float zv = sZ[tt][g];
                float yv = (p + uv * Dd) * silu_f(zv);
                __nv_bfloat16 hi, lo; split_bf16(yv, hi, lo);
                yghi[idx] = hi; yglo[idx] = lo;
            }
        }
    }
}

// ================= launcher =================
extern "C" void kernel_launch(void* const* d_in, const int* in_sizes, int n_in,
                              void* d_out, int out_size) {
    const float* x         = (const float*)d_in[0];
    const float* norm_w    = (const float*)d_in[2];
    const float* in_proj_w = (const float*)d_in[3];
    const float* conv_w    = (const float*)d_in[4];
    const float* conv_b    = (const float*)d_in[5];
    const float* x_proj_w  = (const float*)d_in[6];
    const float* dt_proj_w = (const float*)d_in[7];
    const float* dt_proj_b = (const float*)d_in[8];
    const float* A_log     = (const float*)d_in[9];
    const float* Dp        = (const float*)d_in[10];
    const float* out_proj_w= (const float*)d_in[11];
    float* out = (float*)d_out;

    float *xz, *xd, *xdp, *dt;
    cudaGetSymbolAddress((void**)&xz,  g_xz);
    cudaGetSymbolAddress((void**)&xd,  g_xd);
    cudaGetSymbolAddress((void**)&xdp, g_xdp);
    cudaGetSymbolAddress((void**)&dt,  g_dt);
    __nv_bfloat16 *h_hi, *h_lo, *u_hi, *u_lo, *xd_hi, *xd_lo, *yg_hi, *yg_lo;
    __nv_bfloat16 *wi_hi, *wi_lo, *wx_hi, *wx_lo, *wd_hi, *wd_lo, *wo_hi, *wo_lo;
    cudaGetSymbolAddress((void**)&h_hi,  g_h_hi);  cudaGetSymbolAddress((void**)&h_lo,  g_h_lo);
    cudaGetSymbolAddress((void**)&u_hi,  g_u_hi);  cudaGetSymbolAddress((void**)&u_lo,  g_u_lo);
    cudaGetSymbolAddress((void**)&xd_hi, g_xd_hi); cudaGetSymbolAddress((void**)&xd_lo, g_xd_lo);
    cudaGetSymbolAddress((void**)&yg_hi, g_yg_hi); cudaGetSymbolAddress((void**)&yg_lo, g_yg_lo);
    cudaGetSymbolAddress((void**)&wi_hi, g_wi_hi); cudaGetSymbolAddress((void**)&wi_lo, g_wi_lo);
    cudaGetSymbolAddress((void**)&wx_hi, g_wx_hi); cudaGetSymbolAddress((void**)&wx_lo, g_wx_lo);
    cudaGetSymbolAddress((void**)&wd_hi, g_wd_hi); cudaGetSymbolAddress((void**)&wd_lo, g_wd_lo);
    cudaGetSymbolAddress((void**)&wo_hi, g_wo_hi); cudaGetSymbolAddress((void**)&wo_lo, g_wo_lo);

    cudaFuncSetAttribute(mma_gemm_k<0>, cudaFuncAttributeMaxDynamicSharedMemorySize, SMEMB);
    cudaFuncSetAttribute(mma_gemm_k<1>, cudaFuncAttributeMaxDynamicSharedMemorySize, SMEMB);
    cudaFuncSetAttribute(mma_gemm_k<2>, cudaFuncAttributeMaxDynamicSharedMemorySize, SMEMB);
    cudaFuncSetAttribute(mma_gemm_k<4>, cudaFuncAttributeMaxDynamicSharedMemorySize, SMEMB);

    // 0. weight transpose + bf16 split
    transcvt_k<<<dim3((2*DI)/32, DM/32), 256>>>(in_proj_w, DM, 2*DI, wi_hi, wi_lo);
    transcvt_k<<<dim3(XD/32, DI/32), 256>>>(x_proj_w, DI, XD, wx_hi, wx_lo);
    transcvt_k<<<dim3(DI/32, RR/32), 256>>>(dt_proj_w, RR, DI, wd_hi, wd_lo);
    transcvt_k<<<dim3(DM/32, DI/32), 256>>>(out_proj_w, DI, DM, wo_hi, wo_lo);
    // 1. h = rmsnorm(x) -> bf16 hi/lo
    rmsnorm_k<<<MR, 256>>>(x, norm_w, h_hi, h_lo);
    // 2. xz = h @ in_proj_w  (4096x1024 @ 1024x4096)
    mma_gemm_k<0><<<dim3((2*DI)/128, MR/128), 256, SMEMB>>>(
        h_hi, h_lo, DM, wi_hi, wi_lo, xz, 2*DI, DM, 2*DI, nullptr, nullptr);
    // 3. u = silu(causal_conv(xz[..., :DI])) -> bf16 hi/lo
    conv_silu_k<<<dim3(DI/256, LL/CLT, BB), 256>>>(xz, conv_w, conv_b, u_hi, u_lo);
    // 4. xdbl = u @ x_proj_w  (4096x2048 @ 2048x96), split-K x8 + reduce
    mma_gemm_k<4><<<dim3(1, MR/128, XKS), 256, SMEMB>>>(
        u_hi, u_lo, DI, wx_hi, wx_lo, xdp, XD, DI, XD, nullptr, nullptr);
    xd_reduce_k<<<(MR * XD) / 256, 256>>>(xdp, xd, xd_hi, xd_lo);
    // 5. dt = softplus(xdbl[:, :64] @ dt_proj_w + b)  (4096x64 @ 64x2048)
    mma_gemm_k<1><<<dim3(DI/128, MR/128), 256, SMEMB>>>(
        xd_hi, xd_lo, XD, wd_hi, wd_lo, dt, DI, RR, DI, dt_proj_b, nullptr);
    // 6. selective scan + fused gate -> yg bf16 hi/lo
    scan_k<<<BB * DI / 16, 256>>>(xd, dt, u_hi, u_lo, xz, A_log, Dp, yg_hi, yg_lo);
    // 7. out = x + yg @ out_proj_w  (4096x2048 @ 2048x1024)
    mma_gemm_k<2><<<dim3(DM/128, MR/128), 256, SMEMB>>>(
        yg_hi, yg_lo, DI, wo_hi, wo_lo, out, DM, DI, DM, nullptr, x);
}

// round 8
// speedup vs baseline: 3.4842x; 2.5119x over previous
#include <cuda_runtime.h>
#include <cuda_bf16.h>
#include <math.h>
#include <stdint.h>

// Problem dims
#define BB   2
#define LL   2048
#define DM   1024
#define DI   2048
#define NS   16
#define RR   64
#define XD   96            // R + 2N
#define MR   (BB*LL)       // 4096 rows
#define EPSV 1e-5f
#define XKS  8             // split-K factor for x_proj

// ---------------- scratch (no alloc allowed) ----------------
__device__ __align__(128) float g_xz  [(size_t)MR * 2 * DI];
__device__ __align__(128) float g_xd  [(size_t)MR * XD];
__device__ __align__(128) float g_xdp [(size_t)XKS * MR * XD];  // split-K partials
__device__ __align__(128) float g_dt  [(size_t)MR * DI];
__device__ __align__(128) float g_y   [(size_t)MR * DI];

__device__ __align__(128) __nv_bfloat16 g_h  [(size_t)MR * DM];
__device__ __align__(128) __nv_bfloat16 g_u  [(size_t)MR * DI];
__device__ __align__(128) __nv_bfloat16 g_xdh[(size_t)MR * XD];
__device__ __align__(128) __nv_bfloat16 g_yg [(size_t)MR * DI];
// transposed weights [N,K] bf16
__device__ __align__(128) __nv_bfloat16 g_wi [(size_t)(2*DI) * DM];
__device__ __align__(128) __nv_bfloat16 g_wx [(size_t)XD * DI];
__device__ __align__(128) __nv_bfloat16 g_wd [(size_t)DI * RR];
__device__ __align__(128) __nv_bfloat16 g_wo [(size_t)DM * DI];

// ================= baseline-PTX helpers (no sm_103a-only ops) =============
__device__ __forceinline__ uint32_t smem_to_u32(const void* p) {
    uint32_t a;
    asm("{ .reg .u64 t; cvta.to.shared.u64 t, %1; cvt.u32.u64 %0, t; }" : "=r"(a) : "l"(p));
    return a;
}
#define CP_ASYNC16(dst, src) \
    asm volatile("cp.async.cg.shared.global [%0], [%1], 16;" :: "r"(dst), "l"(src))
#define CP_ASYNC16_P(dst, src, p) \
    asm volatile("{\n\t.reg .pred q;\n\t.reg .b32 sz;\n\t" \
                 "setp.ne.u32 q, %2, 0;\n\tselp.b32 sz, 16, 0, q;\n\t" \
                 "cp.async.cg.shared.global [%0], [%1], 16, sz;\n\t}" \
                 :: "r"(dst), "l"(src), "r"(p))
#define CP_COMMIT() asm volatile("cp.async.commit_group;" ::: "memory")
#define CP_WAIT(N)  asm volatile("cp.async.wait_group %0;" :: "n"(N) : "memory")
#define LDMX4(r0, r1, r2, r3, addr) \
    asm volatile("ldmatrix.sync.aligned.m8n8.x4.shared.b16 {%0,%1,%2,%3}, [%4];" \
                 : "=r"(r0), "=r"(r1), "=r"(r2), "=r"(r3) : "r"(addr))
#define MMA16816(d, a, b) \
    asm volatile("mma.sync.aligned.m16n8k16.row.col.f32.bf16.bf16.f32 " \
                 "{%0,%1,%2,%3}, {%4,%5,%6,%7}, {%8,%9}, {%0,%1,%2,%3};" \
                 : "+f"((d)[0]), "+f"((d)[1]), "+f"((d)[2]), "+f"((d)[3]) \
                 : "r"((a)[0]), "r"((a)[1]), "r"((a)[2]), "r"((a)[3]), \
                   "r"((b)[0]), "r"((b)[1]))

// ---------------- math helpers ----------------
__device__ __forceinline__ float softplus_f(float v) {
    return v > 20.f ? v : log1pf(__expf(v));
}
__device__ __forceinline__ float silu_f(float v) {
    return v / (1.f + __expf(-v));
}

// ================= RMSNorm -> bf16 =================
__global__ void rmsnorm_k(const float* __restrict__ x,
                          const float* __restrict__ w,
                          __nv_bfloat16* __restrict__ oh) {
    int row = blockIdx.x;
    const float4* xr = (const float4*)(x + (size_t)row * DM);
    float4 v = xr[threadIdx.x];
    float ss = v.x*v.x + v.y*v.y + v.z*v.z + v.w*v.w;
    #pragma unroll
    for (int m = 16; m; m >>= 1) ss += __shfl_xor_sync(~0u, ss, m);
    __shared__ float sred[8];
    __shared__ float stot;
    int wid = threadIdx.x >> 5;
    if ((threadIdx.x & 31) == 0) sred[wid] = ss;
    __syncthreads();
    if (threadIdx.x == 0) {
        float s = 0.f;
        #pragma unroll
        for (int i = 0; i < 8; i++) s += sred[i];
        stot = rsqrtf(s * (1.f / DM) + EPSV);
    }
    __syncthreads();
    float sc = stot;
    float4 wv = ((const float4*)w)[threadIdx.x];
    size_t base = (size_t)row * DM + threadIdx.x * 4;
    oh[base + 0] = __float2bfloat16(v.x * sc * wv.x);
    oh[base + 1] = __float2bfloat16(v.y * sc * wv.y);
    oh[base + 2] = __float2bfloat16(v.z * sc * wv.z);
    oh[base + 3] = __float2bfloat16(v.w * sc * wv.w);
}

// ================= transpose + bf16 convert =================
// in [R,C] fp32 -> out [C,R] bf16. R,C multiples of 32.
__global__ void transcvt_k(const float* __restrict__ in, int R, int C,
                           __nv_bfloat16* __restrict__ oh) {
    __shared__ float t[32][33];
    int ct = blockIdx.x * 32, rt = blockIdx.y * 32;
    int tx = threadIdx.x & 31, ty4 = (threadIdx.x >> 5) * 4;
    #pragma unroll
    for (int j = 0; j < 4; j++) {
        int r = rt + ty4 + j;
        t[ty4 + j][tx] = in[(size_t)r * C + ct + tx];
    }
    __syncthreads();
    #pragma unroll
    for (int j = 0; j < 4; j++) {
        int c = ct + ty4 + j;
        size_t o = (size_t)c * R + rt + tx;
        oh[o] = __float2bfloat16(t[tx][ty4 + j]);
    }
}

// ================= HMMA bf16 GEMM, 4-stage cp.async pipeline ==============
// C[M,N] = A[M,K] @ Bt^T, Bt[N,K] bf16, fp32 accum. 128x128 CTA tile, BK=32,
// 8 warps (4x2), warp tile 32x64. SINGLE product (no compensation).
// EPI 0: plain  1: softplus(v+bias[col])  2: v+resid[row,col]
// EPI 4: split-K partial (z slices)
#define SMS    80                    // smem row stride bytes (40 halves)
#define T_B    10240
#define T_STG  20480
#define NSTG   4
#define SMEMB  (NSTG * T_STG)

template<int EPI>
__global__ void __launch_bounds__(256, 1)
mma_gemm_k(const __nv_bfloat16* __restrict__ A, int lda,
           const __nv_bfloat16* __restrict__ Bt,
           float* __restrict__ C, int ldc, int Kdim, int Ndim,
           const float* __restrict__ bias, const float* __restrict__ resid) {
    extern __shared__ char smem[];
    const uint32_t sdata = smem_to_u32(smem);
    const int tid = threadIdx.x;
    const int wid = tid >> 5, lane = tid & 31;
    const int wm = wid & 3, wn = wid >> 2;          // 4 x 2 warp grid
    const int brow = blockIdx.y * 128;
    const int bcol = blockIdx.x * 128;
    const int kslice = Kdim / gridDim.z;            // gridDim.z==1 unless EPI 4
    const int kbase  = blockIdx.z * kslice;
    const int NC = kslice >> 5;                     // 32-wide K chunks

    const int lrow = tid >> 2;
    const int lseg = tid & 3;

    float acc[2][8][4];
    #pragma unroll
    for (int a = 0; a < 2; a++)
        #pragma unroll
        for (int b = 0; b < 8; b++)
            #pragma unroll
            for (int c = 0; c < 4; c++) acc[a][b][c] = 0.f;

    auto issue = [&](int s) {
        uint32_t stb = sdata + (s & (NSTG - 1)) * T_STG;
        int koff = kbase + s * 32;
        #pragma unroll
        for (int it = 0; it < 2; it++) {
            int row = it * 64 + lrow;
            uint32_t so = stb + row * SMS + lseg * 16;
            size_t gao = (size_t)(brow + row) * lda + koff + lseg * 8;
            CP_ASYNC16(so, A + gao);
            int bn = bcol + row;
            uint32_t p = (bn < Ndim) ? 1u : 0u;
            size_t gbo = (size_t)bn * Kdim + koff + lseg * 8;
            CP_ASYNC16_P(so + T_B, Bt + gbo, p);
        }
        CP_COMMIT();
    };

    // prefetch 3 stages
    #pragma unroll
    for (int s = 0; s < NSTG - 1; s++) {
        if (s < NC) issue(s); else CP_COMMIT();
    }

    for (int i = 0; i < NC; i++) {
        CP_WAIT(NSTG - 2);
        __syncthreads();
        if (i + NSTG - 1 < NC) issue(i + NSTG - 1); else CP_COMMIT();

        uint32_t stb = sdata + (i & (NSTG - 1)) * T_STG;
        const int fr = lane & 15;
        const int fc = (lane >> 4) * 8;
        #pragma unroll
        for (int ks = 0; ks < 32; ks += 16) {
            uint32_t ah[2][4], bh[8][2];
            #pragma unroll
            for (int mt = 0; mt < 2; mt++) {
                uint32_t ad = stb + (wm * 32 + mt * 16 + fr) * SMS + (ks + fc) * 2;
                LDMX4(ah[mt][0], ah[mt][1], ah[mt][2], ah[mt][3], ad);
            }
            #pragma unroll
            for (int bt = 0; bt < 4; bt++) {
                uint32_t bd = stb + T_B + (wn * 64 + bt * 16 + fr) * SMS + (ks + fc) * 2;
                uint32_t r0, r1, r2, r3;
                LDMX4(r0, r1, r2, r3, bd);
                bh[bt*2][0] = r0;   bh[bt*2][1] = r2;
                bh[bt*2+1][0] = r1; bh[bt*2+1][1] = r3;
            }
            #pragma unroll
            for (int mt = 0; mt < 2; mt++)
                #pragma unroll
                for (int nt = 0; nt < 8; nt++)
                    MMA16816(acc[mt][nt], ah[mt], bh[nt]);
        }
    }

    // ---- epilogue ----
    float* Cout = C;
    if (EPI == 4) Cout = C + (size_t)blockIdx.z * MR * XD;
    const int lr = lane >> 2;
    const int lc = (lane & 3) * 2;
    #pragma unroll
    for (int mt = 0; mt < 2; mt++) {
        int r0 = brow + wm * 32 + mt * 16 + lr;
        #pragma unroll
        for (int nt = 0; nt < 8; nt++) {
            int c = bcol + wn * 64 + nt * 8 + lc;
            if (c >= Ndim) continue;
            #pragma unroll
            for (int hh = 0; hh < 2; hh++) {
                int r = r0 + hh * 8;
                float v0 = acc[mt][nt][hh*2], v1 = acc[mt][nt][hh*2+1];
                if (EPI == 1) {
                    v0 = softplus_f(v0 + bias[c]);
                    v1 = softplus_f(v1 + bias[c+1]);
                } else if (EPI == 2) {
                    const float* rr = resid + (size_t)r * ldc + c;
                    v0 += rr[0]; v1 += rr[1];
                }
                float* cp = Cout + (size_t)r * ldc + c;
                *(float2*)cp = make_float2(v0, v1);
            }
        }
    }
}

// ================= split-K reduce for x_proj -> xd fp32 + bf16 ============
__global__ void xd_reduce_k(const float* __restrict__ part,
                            float* __restrict__ xd,
                            __nv_bfloat16* __restrict__ xh) {
    size_t i = (size_t)blockIdx.x * 256 + threadIdx.x;
    float s = 0.f;
    #pragma unroll
    for (int z = 0; z < XKS; z++) s += part[(size_t)z * MR * XD + i];
    xd[i] = s;
    xh[i] = __float2bfloat16(s);
}

// ================= causal depthwise conv (K=4) + SiLU, L-tiled -> bf16 ====
#define CLT 16
__global__ void conv_silu_k(const float* __restrict__ xz,
                            const float* __restrict__ cw,
                            const float* __restrict__ cb,
                            __nv_bfloat16* __restrict__ uh) {
    int d = blockIdx.x * 256 + threadIdx.x;
    int l0 = blockIdx.y * CLT;
    int b = blockIdx.z;
    float4 w = ((const float4*)cw)[d];
    float bias = cb[d];
    const size_t stride = (size_t)2 * DI;
    size_t base = ((size_t)(b * LL) + l0) * stride + d;
    float i3 = (l0 >= 3) ? xz[base - 3 * stride] : 0.f;
    float i2 = (l0 >= 2) ? xz[base - 2 * stride] : 0.f;
    float i1 = (l0 >= 1) ? xz[base - 1 * stride] : 0.f;
    size_t ob = ((size_t)(b * LL) + l0) * DI + d;
    #pragma unroll
    for (int j = 0; j < CLT; j++) {
        float cur = xz[base + (size_t)j * stride];
        float acc = bias;
        acc = fmaf(i3, w.x, acc);
        acc = fmaf(i2, w.y, acc);
        acc = fmaf(i1, w.z, acc);
        acc = fmaf(cur, w.w, acc);
        uh[ob + (size_t)j * DI] = __float2bfloat16(silu_f(acc));
        i3 = i2; i2 = i1; i1 = cur;
    }
}

// ================= selective scan -> y fp32 =================
__global__ void __launch_bounds__(256) scan_k(
    const float* __restrict__ xdbl, const float* __restrict__ dt,
    const __nv_bfloat16* __restrict__ uh,
    const float* __restrict__ Alog, const float* __restrict__ Dp,
    float* __restrict__ y) {
    __shared__ float sBC[64][32];
    int tid = threadIdx.x;
    int g = tid >> 4, n = tid & 15;
    int b = blockIdx.x >> 7;
    int d = ((blockIdx.x & 127) << 4) + g;
    float An = -expf(Alog[d * NS + n]);
    float Dd = Dp[d];
    float h = 0.f;
    size_t rowbase = (size_t)b * LL;
    for (int c = 0; c < LL / 64; c++) {
        __syncthreads();
        for (int i = tid; i < 64 * 32; i += 256) {
            int tt = i >> 5, col = i & 31;
            sBC[tt][col] = xdbl[(rowbase + c * 64 + tt) * XD + 64 + col];
        }
        __syncthreads();
        for (int tt = 0; tt < 64; tt++) {
            size_t idx = (rowbase + c * 64 + tt) * DI + d;
            float dtv = __ldg(dt + idx);
            float uv  = __bfloat162float(uh[idx]);
            float Bv = sBC[tt][n];
            float Cv = sBC[tt][16 + n];
            float dA = __expf(dtv * An);
            h = fmaf(dA, h, dtv * Bv * uv);
            float p = h * Cv;
            p += __shfl_xor_sync(0xffffffffu, p, 8, 16);
            p += __shfl_xor_sync(0xffffffffu, p, 4, 16);
            p += __shfl_xor_sync(0xffffffffu, p, 2, 16);
            p += __shfl_xor_sync(0xffffffffu, p, 1, 16);
            if (n == 0) y[idx] = p + uv * Dd;
        }
    }
}

// ================= gate: yg = y * silu(z) -> bf16 =================
__global__ void gate_k(const float* __restrict__ xz, const float* __restrict__ y,
                       __nv_bfloat16* __restrict__ gh) {
    size_t i = (size_t)blockIdx.x * blockDim.x + threadIdx.x;  // over MR*DI/4
    size_t m = i >> 9;
    size_t c = i & 511;
    float4 z  = ((const float4*)xz)[m * 1024 + 512 + c];
    float4 yv = ((const float4*)y)[i];
    size_t base = i * 4;
    gh[base + 0] = __float2bfloat16(yv.x * silu_f(z.x));
    gh[base + 1] = __float2bfloat16(yv.y * silu_f(z.y));
    gh[base + 2] = __float2bfloat16(yv.z * silu_f(z.z));
    gh[base + 3] = __float2bfloat16(yv.w * silu_f(z.w));
}

// ================= launcher =================
extern "C" void kernel_launch(void* const* d_in, const int* in_sizes, int n_in,
                              void* d_out, int out_size) {
    const float* x         = (const float*)d_in[0];
    const float* norm_w    = (const float*)d_in[2];
    const float* in_proj_w = (const float*)d_in[3];
    const float* conv_w    = (const float*)d_in[4];
    const float* conv_b    = (const float*)d_in[5];
    const float* x_proj_w  = (const float*)d_in[6];
    const float* dt_proj_w = (const float*)d_in[7];
    const float* dt_proj_b = (const float*)d_in[8];
    const float* A_log     = (const float*)d_in[9];
    const float* Dp        = (const float*)d_in[10];
    const float* out_proj_w= (const float*)d_in[11];
    float* out = (float*)d_out;

    float *xz, *xd, *xdp, *dt, *y;
    cudaGetSymbolAddress((void**)&xz,  g_xz);
    cudaGetSymbolAddress((void**)&xd,  g_xd);
    cudaGetSymbolAddress((void**)&xdp, g_xdp);
    cudaGetSymbolAddress((void**)&dt,  g_dt);
    cudaGetSymbolAddress((void**)&y,   g_y);
    __nv_bfloat16 *hh, *uh, *xdh, *yg, *wi, *wx, *wd, *wo;
    cudaGetSymbolAddress((void**)&hh,  g_h);
    cudaGetSymbolAddress((void**)&uh,  g_u);
    cudaGetSymbolAddress((void**)&xdh, g_xdh);
    cudaGetSymbolAddress((void**)&yg,  g_yg);
    cudaGetSymbolAddress((void**)&wi,  g_wi);
    cudaGetSymbolAddress((void**)&wx,  g_wx);
    cudaGetSymbolAddress((void**)&wd,  g_wd);
    cudaGetSymbolAddress((void**)&wo,  g_wo);

    cudaFuncSetAttribute(mma_gemm_k<0>, cudaFuncAttributeMaxDynamicSharedMemorySize, SMEMB);
    cudaFuncSetAttribute(mma_gemm_k<1>, cudaFuncAttributeMaxDynamicSharedMemorySize, SMEMB);
    cudaFuncSetAttribute(mma_gemm_k<2>, cudaFuncAttributeMaxDynamicSharedMemorySize, SMEMB);
    cudaFuncSetAttribute(mma_gemm_k<4>, cudaFuncAttributeMaxDynamicSharedMemorySize, SMEMB);

    // 0. weight transpose + bf16 convert
    transcvt_k<<<dim3((2*DI)/32, DM/32), 256>>>(in_proj_w, DM, 2*DI, wi);
    transcvt_k<<<dim3(XD/32, DI/32), 256>>>(x_proj_w, DI, XD, wx);
    transcvt_k<<<dim3(DI/32, RR/32), 256>>>(dt_proj_w, RR, DI, wd);
    transcvt_k<<<dim3(DM/32, DI/32), 256>>>(out_proj_w, DI, DM, wo);
    // 1. h = rmsnorm(x) -> bf16
    rmsnorm_k<<<MR, 256>>>(x, norm_w, hh);
    // 2. xz = h @ in_proj_w  (4096x1024 @ 1024x4096)
    mma_gemm_k<0><<<dim3((2*DI)/128, MR/128), 256, SMEMB>>>(
        hh, DM, wi, xz, 2*DI, DM, 2*DI, nullptr, nullptr);
    // 3. u = silu(causal_conv(xz[..., :DI])) -> bf16
    conv_silu_k<<<dim3(DI/256, LL/CLT, BB), 256>>>(xz, conv_w, conv_b, uh);
    // 4. xdbl = u @ x_proj_w  (4096x2048 @ 2048x96), split-K x8 + reduce
    mma_gemm_k<4><<<dim3(1, MR/128, XKS), 256, SMEMB>>>(
        uh, DI, wx, xdp, XD, DI, XD, nullptr, nullptr);
    xd_reduce_k<<<(MR * XD) / 256, 256>>>(xdp, xd, xdh);
    // 5. dt = softplus(xdbl[:, :64] @ dt_proj_w + b)  (4096x64 @ 64x2048)
    mma_gemm_k<1><<<dim3(DI/128, MR/128), 256, SMEMB>>>(
        xdh, XD, wd, dt, DI, RR, DI, dt_proj_b, nullptr);
    // 6. selective scan -> y fp32 (includes + u*D)
    scan_k<<<BB * DI / 16, 256>>>(xd, dt, uh, A_log, Dp, y);
    // 7. yg = y * silu(z) -> bf16
    gate_k<<<(MR * DI / 4) / 256, 256>>>(xz, y, yg);
    // 8. out = x + yg @ out_proj_w  (4096x2048 @ 2048x1024)
    mma_gemm_k<2><<<dim3(DM/128, MR/128), 256, SMEMB>>>(
        yg, DI, wo, out, DM, DI, DM, nullptr, x);
}

// round 9
// speedup vs baseline: 5.7281x; 1.6440x over previous
#include <cuda_runtime.h>
#include <cuda_bf16.h>
#include <math.h>
#include <stdint.h>

// Problem dims
#define BB   2
#define LL   2048
#define DM   1024
#define DI   2048
#define NS   16
#define RR   64
#define XD   96            // R + 2N
#define MR   (BB*LL)       // 4096 rows
#define EPSV 1e-5f
#define XKS  8             // split-K factor for x_proj

// ---------------- scratch (no alloc allowed) ----------------
__device__ __align__(128) float g_xz  [(size_t)MR * 2 * DI];
__device__ __align__(128) float g_xd  [(size_t)MR * XD];
__device__ __align__(128) float g_xdp [(size_t)XKS * MR * XD];  // split-K partials
__device__ __align__(128) float g_dt  [(size_t)MR * DI];
__device__ __align__(128) float g_y   [(size_t)MR * DI];

__device__ __align__(128) __nv_bfloat16 g_h  [(size_t)MR * DM];
__device__ __align__(128) __nv_bfloat16 g_u  [(size_t)MR * DI];
__device__ __align__(128) __nv_bfloat16 g_xdh[(size_t)MR * XD];
__device__ __align__(128) __nv_bfloat16 g_yg [(size_t)MR * DI];
// transposed weights [N,K] bf16
__device__ __align__(128) __nv_bfloat16 g_wi [(size_t)(2*DI) * DM];
__device__ __align__(128) __nv_bfloat16 g_wx [(size_t)XD * DI];
__device__ __align__(128) __nv_bfloat16 g_wd [(size_t)DI * RR];
__device__ __align__(128) __nv_bfloat16 g_wo [(size_t)DM * DI];

// ================= baseline-PTX helpers (no sm_103a-only ops) =============
__device__ __forceinline__ uint32_t smem_to_u32(const void* p) {
    uint32_t a;
    asm("{ .reg .u64 t; cvta.to.shared.u64 t, %1; cvt.u32.u64 %0, t; }" : "=r"(a) : "l"(p));
    return a;
}
#define CP_ASYNC16(dst, src) \
    asm volatile("cp.async.cg.shared.global [%0], [%1], 16;" :: "r"(dst), "l"(src))
#define CP_ASYNC16_P(dst, src, p) \
    asm volatile("{\n\t.reg .pred q;\n\t.reg .b32 sz;\n\t" \
                 "setp.ne.u32 q, %2, 0;\n\tselp.b32 sz, 16, 0, q;\n\t" \
                 "cp.async.cg.shared.global [%0], [%1], 16, sz;\n\t}" \
                 :: "r"(dst), "l"(src), "r"(p))
#define CP_COMMIT() asm volatile("cp.async.commit_group;" ::: "memory")
#define CP_WAIT(N)  asm volatile("cp.async.wait_group %0;" :: "n"(N) : "memory")
#define LDMX4(r0, r1, r2, r3, addr) \
    asm volatile("ldmatrix.sync.aligned.m8n8.x4.shared.b16 {%0,%1,%2,%3}, [%4];" \
                 : "=r"(r0), "=r"(r1), "=r"(r2), "=r"(r3) : "r"(addr))
#define MMA16816(d, a, b) \
    asm volatile("mma.sync.aligned.m16n8k16.row.col.f32.bf16.bf16.f32 " \
                 "{%0,%1,%2,%3}, {%4,%5,%6,%7}, {%8,%9}, {%0,%1,%2,%3};" \
                 : "+f"((d)[0]), "+f"((d)[1]), "+f"((d)[2]), "+f"((d)[3]) \
                 : "r"((a)[0]), "r"((a)[1]), "r"((a)[2]), "r"((a)[3]), \
                   "r"((b)[0]), "r"((b)[1]))

// ---------------- math helpers ----------------
__device__ __forceinline__ float softplus_f(float v) {
    return v > 20.f ? v : log1pf(__expf(v));
}
__device__ __forceinline__ float silu_f(float v) {
    return v / (1.f + __expf(-v));
}

// ================= RMSNorm -> bf16 =================
__global__ void rmsnorm_k(const float* __restrict__ x,
                          const float* __restrict__ w,
                          __nv_bfloat16* __restrict__ oh) {
    int row = blockIdx.x;
    const float4* xr = (const float4*)(x + (size_t)row * DM);
    float4 v = xr[threadIdx.x];
    float ss = v.x*v.x + v.y*v.y + v.z*v.z + v.w*v.w;
    #pragma unroll
    for (int m = 16; m; m >>= 1) ss += __shfl_xor_sync(~0u, ss, m);
    __shared__ float sred[8];
    __shared__ float stot;
    int wid = threadIdx.x >> 5;
    if ((threadIdx.x & 31) == 0) sred[wid] = ss;
    __syncthreads();
    if (threadIdx.x == 0) {
        float s = 0.f;
        #pragma unroll
        for (int i = 0; i < 8; i++) s += sred[i];
        stot = rsqrtf(s * (1.f / DM) + EPSV);
    }
    __syncthreads();
    float sc = stot;
    float4 wv = ((const float4*)w)[threadIdx.x];
    size_t base = (size_t)row * DM + threadIdx.x * 4;
    oh[base + 0] = __float2bfloat16(v.x * sc * wv.x);
    oh[base + 1] = __float2bfloat16(v.y * sc * wv.y);
    oh[base + 2] = __float2bfloat16(v.z * sc * wv.z);
    oh[base + 3] = __float2bfloat16(v.w * sc * wv.w);
}

// ================= transpose + bf16 convert =================
// in [R,C] fp32 -> out [C,R] bf16. R,C multiples of 32.
__global__ void transcvt_k(const float* __restrict__ in, int R, int C,
                           __nv_bfloat16* __restrict__ oh) {
    __shared__ float t[32][33];
    int ct = blockIdx.x * 32, rt = blockIdx.y * 32;
    int tx = threadIdx.x & 31, ty4 = (threadIdx.x >> 5) * 4;
    #pragma unroll
    for (int j = 0; j < 4; j++) {
        int r = rt + ty4 + j;
        t[ty4 + j][tx] = in[(size_t)r * C + ct + tx];
    }
    __syncthreads();
    #pragma unroll
    for (int j = 0; j < 4; j++) {
        int c = ct + ty4 + j;
        size_t o = (size_t)c * R + rt + tx;
        oh[o] = __float2bfloat16(t[tx][ty4 + j]);
    }
}

// ================= HMMA bf16 GEMM, 4-stage cp.async pipeline ==============
// C[M,N] = A[M,K] @ Bt^T, Bt[N,K] bf16, fp32 accum. 128x128 CTA tile, BK=32,
// 8 warps (4x2), warp tile 32x64. SINGLE product.
// EPI 0: plain  1: softplus(v+bias[col])  2: v+resid[row,col]
// EPI 4: split-K partial (z slices)
#define SMS    80                    // smem row stride bytes (40 halves)
#define T_B    10240
#define T_STG  20480
#define NSTG   4
#define SMEMB  (NSTG * T_STG)

template<int EPI>
__global__ void __launch_bounds__(256, 1)
mma_gemm_k(const __nv_bfloat16* __restrict__ A, int lda,
           const __nv_bfloat16* __restrict__ Bt,
           float* __restrict__ C, int ldc, int Kdim, int Ndim,
           const float* __restrict__ bias, const float* __restrict__ resid) {
    extern __shared__ char smem[];
    const uint32_t sdata = smem_to_u32(smem);
    const int tid = threadIdx.x;
    const int wid = tid >> 5, lane = tid & 31;
    const int wm = wid & 3, wn = wid >> 2;          // 4 x 2 warp grid
    const int brow = blockIdx.y * 128;
    const int bcol = blockIdx.x * 128;
    const int kslice = Kdim / gridDim.z;            // gridDim.z==1 unless EPI 4
    const int kbase  = blockIdx.z * kslice;
    const int NC = kslice >> 5;                     // 32-wide K chunks

    const int lrow = tid >> 2;
    const int lseg = tid & 3;

    float acc[2][8][4];
    #pragma unroll
    for (int a = 0; a < 2; a++)
        #pragma unroll
        for (int b = 0; b < 8; b++)
            #pragma unroll
            for (int c = 0; c < 4; c++) acc[a][b][c] = 0.f;

    auto issue = [&](int s) {
        uint32_t stb = sdata + (s & (NSTG - 1)) * T_STG;
        int koff = kbase + s * 32;
        #pragma unroll
        for (int it = 0; it < 2; it++) {
            int row = it * 64 + lrow;
            uint32_t so = stb + row * SMS + lseg * 16;
            size_t gao = (size_t)(brow + row) * lda + koff + lseg * 8;
            CP_ASYNC16(so, A + gao);
            int bn = bcol + row;
            uint32_t p = (bn < Ndim) ? 1u : 0u;
            size_t gbo = (size_t)bn * Kdim + koff + lseg * 8;
            CP_ASYNC16_P(so + T_B, Bt + gbo, p);
        }
        CP_COMMIT();
    };

    // prefetch 3 stages
    #pragma unroll
    for (int s = 0; s < NSTG - 1; s++) {
        if (s < NC) issue(s); else CP_COMMIT();
    }

    for (int i = 0; i < NC; i++) {
        CP_WAIT(NSTG - 2);
        __syncthreads();
        if (i + NSTG - 1 < NC) issue(i + NSTG - 1); else CP_COMMIT();

        uint32_t stb = sdata + (i & (NSTG - 1)) * T_STG;
        const int fr = lane & 15;
        const int fc = (lane >> 4) * 8;
        #pragma unroll
        for (int ks = 0; ks < 32; ks += 16) {
            uint32_t ah[2][4], bh[8][2];
            #pragma unroll
            for (int mt = 0; mt < 2; mt++) {
                uint32_t ad = stb + (wm * 32 + mt * 16 + fr) * SMS + (ks + fc) * 2;
                LDMX4(ah[mt][0], ah[mt][1], ah[mt][2], ah[mt][3], ad);
            }
            #pragma unroll
            for (int bt = 0; bt < 4; bt++) {
                uint32_t bd = stb + T_B + (wn * 64 + bt * 16 + fr) * SMS + (ks + fc) * 2;
                uint32_t r0, r1, r2, r3;
                LDMX4(r0, r1, r2, r3, bd);
                bh[bt*2][0] = r0;   bh[bt*2][1] = r2;
                bh[bt*2+1][0] = r1; bh[bt*2+1][1] = r3;
            }
            #pragma unroll
            for (int mt = 0; mt < 2; mt++)
                #pragma unroll
                for (int nt = 0; nt < 8; nt++)
                    MMA16816(acc[mt][nt], ah[mt], bh[nt]);
        }
    }

    // ---- epilogue ----
    float* Cout = C;
    if (EPI == 4) Cout = C + (size_t)blockIdx.z * MR * XD;
    const int lr = lane >> 2;
    const int lc = (lane & 3) * 2;
    #pragma unroll
    for (int mt = 0; mt < 2; mt++) {
        int r0 = brow + wm * 32 + mt * 16 + lr;
        #pragma unroll
        for (int nt = 0; nt < 8; nt++) {
            int c = bcol + wn * 64 + nt * 8 + lc;
            if (c >= Ndim) continue;
            #pragma unroll
            for (int hh = 0; hh < 2; hh++) {
                int r = r0 + hh * 8;
                float v0 = acc[mt][nt][hh*2], v1 = acc[mt][nt][hh*2+1];
                if (EPI == 1) {
                    v0 = softplus_f(v0 + bias[c]);
                    v1 = softplus_f(v1 + bias[c+1]);
                } else if (EPI == 2) {
                    const float* rr = resid + (size_t)r * ldc + c;
                    v0 += rr[0]; v1 += rr[1];
                }
                float* cp = Cout + (size_t)r * ldc + c;
                *(float2*)cp = make_float2(v0, v1);
            }
        }
    }
}

// ================= split-K reduce for x_proj -> xd fp32 + bf16 ============
__global__ void xd_reduce_k(const float* __restrict__ part,
                            float* __restrict__ xd,
                            __nv_bfloat16* __restrict__ xh) {
    size_t i = (size_t)blockIdx.x * 256 + threadIdx.x;
    float s = 0.f;
    #pragma unroll
    for (int z = 0; z < XKS; z++) s += part[(size_t)z * MR * XD + i];
    xd[i] = s;
    xh[i] = __float2bfloat16(s);
}

// ================= causal depthwise conv (K=4) + SiLU, L-tiled -> bf16 ====
#define CLT 16
__global__ void conv_silu_k(const float* __restrict__ xz,
                            const float* __restrict__ cw,
                            const float* __restrict__ cb,
                            __nv_bfloat16* __restrict__ uh) {
    int d = blockIdx.x * 256 + threadIdx.x;
    int l0 = blockIdx.y * CLT;
    int b = blockIdx.z;
    float4 w = ((const float4*)cw)[d];
    float bias = cb[d];
    const size_t stride = (size_t)2 * DI;
    size_t base = ((size_t)(b * LL) + l0) * stride + d;
    float i3 = (l0 >= 3) ? xz[base - 3 * stride] : 0.f;
    float i2 = (l0 >= 2) ? xz[base - 2 * stride] : 0.f;
    float i1 = (l0 >= 1) ? xz[base - 1 * stride] : 0.f;
    size_t ob = ((size_t)(b * LL) + l0) * DI + d;
    #pragma unroll
    for (int j = 0; j < CLT; j++) {
        float cur = xz[base + (size_t)j * stride];
        float acc = bias;
        acc = fmaf(i3, w.x, acc);
        acc = fmaf(i2, w.y, acc);
        acc = fmaf(i1, w.z, acc);
        acc = fmaf(cur, w.w, acc);
        uh[ob + (size_t)j * DI] = __float2bfloat16(silu_f(acc));
        i3 = i2; i2 = i1; i1 = cur;
    }
}

// ================= selective scan -> y fp32 =================
// 16 chains per block; lane n of each 16-lane group owns state n.
// dt, u, B, C all staged in SMEM per 64-step chunk so the serial recurrence
// never touches global memory.
__global__ void __launch_bounds__(256) scan_k(
    const float* __restrict__ xdbl, const float* __restrict__ dt,
    const __nv_bfloat16* __restrict__ uh,
    const float* __restrict__ Alog, const float* __restrict__ Dp,
    float* __restrict__ y) {
    __shared__ float sBC[64][32];
    __shared__ float sDT[64][16];
    __shared__ float sU [64][16];
    int tid = threadIdx.x;
    int g = tid >> 4, n = tid & 15;
    int b = blockIdx.x >> 7;
    int d0 = (blockIdx.x & 127) << 4;
    int d = d0 + g;
    float An = -expf(Alog[d * NS + n]);
    float Dd = Dp[d];
    float h = 0.f;
    size_t rowbase = (size_t)b * LL;
    for (int c = 0; c < LL / 64; c++) {
        __syncthreads();
        // stage B/C (coalesced 128B rows)
        for (int i = tid; i < 64 * 32; i += 256) {
            int tt = i >> 5, col = i & 31;
            sBC[tt][col] = xdbl[(rowbase + c * 64 + tt) * XD + 64 + col];
        }
        // stage dt (16 consecutive floats per row) and u (bf16 -> fp32)
        for (int i = tid; i < 64 * 16; i += 256) {
            int tt = i >> 4, col = i & 15;
            size_t ridx = (rowbase + c * 64 + tt) * DI + d0 + col;
            sDT[tt][col] = dt[ridx];
            sU [tt][col] = __bfloat162float(uh[ridx]);
        }
        __syncthreads();
        #pragma unroll 4
        for (int tt = 0; tt < 64; tt++) {
            float dtv = sDT[tt][g];
            float uv  = sU [tt][g];
            float Bv = sBC[tt][n];
            float Cv = sBC[tt][16 + n];
            float dA = __expf(dtv * An);
            h = fmaf(dA, h, dtv * Bv * uv);
            float p = h * Cv;
            p += __shfl_xor_sync(0xffffffffu, p, 8, 16);
            p += __shfl_xor_sync(0xffffffffu, p, 4, 16);
            p += __shfl_xor_sync(0xffffffffu, p, 2, 16);
            p += __shfl_xor_sync(0xffffffffu, p, 1, 16);
            if (n == 0) {
                size_t idx = (rowbase + c * 64 + tt) * DI + d;
                y[idx] = p + uv * Dd;
            }
        }
    }
}

// ================= gate: yg = y * silu(z) -> bf16 =================
__global__ void gate_k(const float* __restrict__ xz, const float* __restrict__ y,
                       __nv_bfloat16* __restrict__ gh) {
    size_t i = (size_t)blockIdx.x * blockDim.x + threadIdx.x;  // over MR*DI/4
    size_t m = i >> 9;
    size_t c = i & 511;
    float4 z  = ((const float4*)xz)[m * 1024 + 512 + c];
    float4 yv = ((const float4*)y)[i];
    size_t base = i * 4;
    gh[base + 0] = __float2bfloat16(yv.x * silu_f(z.x));
    gh[base + 1] = __float2bfloat16(yv.y * silu_f(z.y));
    gh[base + 2] = __float2bfloat16(yv.z * silu_f(z.z));
    gh[base + 3] = __float2bfloat16(yv.w * silu_f(z.w));
}

// ================= launcher =================
extern "C" void kernel_launch(void* const* d_in, const int* in_sizes, int n_in,
                              void* d_out, int out_size) {
    const float* x         = (const float*)d_in[0];
    const float* norm_w    = (const float*)d_in[2];
    const float* in_proj_w = (const float*)d_in[3];
    const float* conv_w    = (const float*)d_in[4];
    const float* conv_b    = (const float*)d_in[5];
    const float* x_proj_w  = (const float*)d_in[6];
    const float* dt_proj_w = (const float*)d_in[7];
    const float* dt_proj_b = (const float*)d_in[8];
    const float* A_log     = (const float*)d_in[9];
    const float* Dp        = (const float*)d_in[10];
    const float* out_proj_w= (const float*)d_in[11];
    float* out = (float*)d_out;

    float *xz, *xd, *xdp, *dt, *y;
    cudaGetSymbolAddress((void**)&xz,  g_xz);
    cudaGetSymbolAddress((void**)&xd,  g_xd);
    cudaGetSymbolAddress((void**)&xdp, g_xdp);
    cudaGetSymbolAddress((void**)&dt,  g_dt);
    cudaGetSymbolAddress((void**)&y,   g_y);
    __nv_bfloat16 *hh, *uh, *xdh, *yg, *wi, *wx, *wd, *wo;
    cudaGetSymbolAddress((void**)&hh,  g_h);
    cudaGetSymbolAddress((void**)&uh,  g_u);
    cudaGetSymbolAddress((void**)&xdh, g_xdh);
    cudaGetSymbolAddress((void**)&yg,  g_yg);
    cudaGetSymbolAddress((void**)&wi,  g_wi);
    cudaGetSymbolAddress((void**)&wx,  g_wx);
    cudaGetSymbolAddress((void**)&wd,  g_wd);
    cudaGetSymbolAddress((void**)&wo,  g_wo);

    cudaFuncSetAttribute(mma_gemm_k<0>, cudaFuncAttributeMaxDynamicSharedMemorySize, SMEMB);
    cudaFuncSetAttribute(mma_gemm_k<1>, cudaFuncAttributeMaxDynamicSharedMemorySize, SMEMB);
    cudaFuncSetAttribute(mma_gemm_k<2>, cudaFuncAttributeMaxDynamicSharedMemorySize, SMEMB);
    cudaFuncSetAttribute(mma_gemm_k<4>, cudaFuncAttributeMaxDynamicSharedMemorySize, SMEMB);

    // 0. weight transpose + bf16 convert
    transcvt_k<<<dim3((2*DI)/32, DM/32), 256>>>(in_proj_w, DM, 2*DI, wi);
    transcvt_k<<<dim3(XD/32, DI/32), 256>>>(x_proj_w, DI, XD, wx);
    transcvt_k<<<dim3(DI/32, RR/32), 256>>>(dt_proj_w, RR, DI, wd);
    transcvt_k<<<dim3(DM/32, DI/32), 256>>>(out_proj_w, DI, DM, wo);
    // 1. h = rmsnorm(x) -> bf16
    rmsnorm_k<<<MR, 256>>>(x, norm_w, hh);
    // 2. xz = h @ in_proj_w  (4096x1024 @ 1024x4096)
    mma_gemm_k<0><<<dim3((2*DI)/128, MR/128), 256, SMEMB>>>(
        hh, DM, wi, xz, 2*DI, DM, 2*DI, nullptr, nullptr);
    // 3. u = silu(causal_conv(xz[..., :DI])) -> bf16
    conv_silu_k<<<dim3(DI/256, LL/CLT, BB), 256>>>(xz, conv_w, conv_b, uh);
    // 4. xdbl = u @ x_proj_w  (4096x2048 @ 2048x96), split-K x8 + reduce
    mma_gemm_k<4><<<dim3(1, MR/128, XKS), 256, SMEMB>>>(
        uh, DI, wx, xdp, XD, DI, XD, nullptr, nullptr);
    xd_reduce_k<<<(MR * XD) / 256, 256>>>(xdp, xd, xdh);
    // 5. dt = softplus(xdbl[:, :64] @ dt_proj_w + b)  (4096x64 @ 64x2048)
    mma_gemm_k<1><<<dim3(DI/128, MR/128), 256, SMEMB>>>(
        xdh, XD, wd, dt, DI, RR, DI, dt_proj_b, nullptr);
    // 6. selective scan -> y fp32 (includes + u*D)
    scan_k<<<BB * DI / 16, 256>>>(xd, dt, uh, A_log, Dp, y);
    // 7. yg = y * silu(z) -> bf16
    gate_k<<<(MR * DI / 4) / 256, 256>>>(xz, y, yg);
    // 8. out = x + yg @ out_proj_w  (4096x2048 @ 2048x1024)
    mma_gemm_k<2><<<dim3(DM/128, MR/128), 256, SMEMB>>>(
        yg, DI, wo, out, DM, DI, DM, nullptr, x);
}